// round 1
// baseline (speedup 1.0000x reference)
#include <cuda_runtime.h>
#include <cstdint>

#define N_NODES 50000
#define E_EDGES 800000
#define DIM 128
#define HEADS 8
#define NEG_SLOPE 0.15f
#define MT 64          // node tile for GEMM
#define MAXE 96        // cached edges per destination in agg kernel

// ---------------- device scratch (no allocations allowed) ----------------
__device__ float g_xl[(size_t)N_NODES * DIM];
__device__ float g_xr[(size_t)N_NODES * DIM];
__device__ int   g_deg[N_NODES];
__device__ int   g_start[N_NODES];
__device__ int   g_cursor[N_NODES];
__device__ int   g_src[E_EDGES];
__device__ int   g_counter;

// ---------------- CSR build ----------------
__global__ void zero_kernel() {
    int i = blockIdx.x * blockDim.x + threadIdx.x;
    if (i < N_NODES) g_deg[i] = 0;
    if (i == 0) g_counter = 0;
}

__global__ void count_kernel(const int* __restrict__ ei) {
    int e = blockIdx.x * blockDim.x + threadIdx.x;
    if (e < E_EDGES) atomicAdd(&g_deg[ei[E_EDGES + e]], 1);
}

__global__ void assign_kernel() {
    int n = blockIdx.x * blockDim.x + threadIdx.x;
    if (n < N_NODES) {
        int d = g_deg[n];
        int s = atomicAdd(&g_counter, d);
        g_start[n]  = s;
        g_cursor[n] = s;
    }
}

__global__ void fill_kernel(const int* __restrict__ ei) {
    int e = blockIdx.x * blockDim.x + threadIdx.x;
    if (e < E_EDGES) {
        int s = ei[e];
        int d = ei[E_EDGES + e];
        int p = atomicAdd(&g_cursor[d], 1);
        g_src[p] = s;
    }
}

// ---------------- LayerNorm + dual GEMM (xl = h@Wl+bl, xr = h@Wr+br) ----------------
// Block: 256 threads, tile = 64 nodes x 256 output cols (cols 0..127 -> xl, 128..255 -> xr)
// Full K=128 in smem. W (128x256) + h tile (64x128) both in smem.
__global__ __launch_bounds__(256, 1)
void ln_gemm_kernel(const float* __restrict__ x,
                    const float* __restrict__ ln_g, const float* __restrict__ ln_b,
                    const float* __restrict__ Wl, const float* __restrict__ bl,
                    const float* __restrict__ Wr, const float* __restrict__ br)
{
    extern __shared__ float smem[];
    float* ws = smem;                // [128][256]
    float* hs = smem + 128 * 256;    // [64][128]

    const int tid  = threadIdx.x;
    const int base = blockIdx.x * MT;

    // Load concatenated weights into smem (coalesced per-row)
    {
        const float* wsrc = (tid < 128) ? Wl : Wr;
        const int col = tid & 127;
        #pragma unroll 4
        for (int k = 0; k < 128; k++)
            ws[k * 256 + tid] = wsrc[k * 128 + col];
    }

    // LayerNorm: one warp per node, lane owns 4 dims
    const int warp = tid >> 5, lane = tid & 31;
    const float4 gv = reinterpret_cast<const float4*>(ln_g)[lane];
    const float4 bv = reinterpret_cast<const float4*>(ln_b)[lane];
    #pragma unroll 1
    for (int i = 0; i < 8; i++) {
        const int nl = i * 8 + warp;
        const int n  = base + nl;
        float4 v = make_float4(0.f, 0.f, 0.f, 0.f);
        if (n < N_NODES)
            v = reinterpret_cast<const float4*>(x + (size_t)n * DIM)[lane];
        float s = v.x + v.y + v.z + v.w;
        #pragma unroll
        for (int w = 16; w; w >>= 1) s += __shfl_xor_sync(0xffffffffu, s, w);
        const float mu = s * (1.0f / 128.0f);
        const float dx = v.x - mu, dy = v.y - mu, dz = v.z - mu, dw = v.w - mu;
        float q = dx * dx + dy * dy + dz * dz + dw * dw;
        #pragma unroll
        for (int w = 16; w; w >>= 1) q += __shfl_xor_sync(0xffffffffu, q, w);
        const float rs = rsqrtf(q * (1.0f / 128.0f) + 1e-5f);
        float4 h;
        h.x = dx * rs * gv.x + bv.x;
        h.y = dy * rs * gv.y + bv.y;
        h.z = dz * rs * gv.z + bv.z;
        h.w = dw * rs * gv.w + bv.w;
        reinterpret_cast<float4*>(hs + nl * DIM)[lane] = h;
    }
    __syncthreads();

    // Register-tiled GEMM: thread computes 8 rows x 8 cols
    const int col0 = (tid & 31) * 8;
    const int row0 = (tid >> 5) * 8;
    float acc[8][8];
    #pragma unroll
    for (int i = 0; i < 8; i++)
        #pragma unroll
        for (int j = 0; j < 8; j++) acc[i][j] = 0.f;

    #pragma unroll 2
    for (int k = 0; k < 128; k++) {
        float hr[8];
        #pragma unroll
        for (int i = 0; i < 8; i++) hr[i] = hs[(row0 + i) * DIM + k];
        const float4 wa = *reinterpret_cast<const float4*>(&ws[k * 256 + col0]);
        const float4 wb = *reinterpret_cast<const float4*>(&ws[k * 256 + col0 + 4]);
        const float wv[8] = {wa.x, wa.y, wa.z, wa.w, wb.x, wb.y, wb.z, wb.w};
        #pragma unroll
        for (int i = 0; i < 8; i++)
            #pragma unroll
            for (int j = 0; j < 8; j++)
                acc[i][j] = fmaf(hr[i], wv[j], acc[i][j]);
    }

    // Store with bias
    const bool is_l = (col0 < 128);
    const float* bb = is_l ? bl : br;
    const int c = is_l ? col0 : (col0 - 128);
    const float4 b0 = *reinterpret_cast<const float4*>(&bb[c]);
    const float4 b1 = *reinterpret_cast<const float4*>(&bb[c + 4]);
    float* dst = is_l ? g_xl : g_xr;
    #pragma unroll
    for (int i = 0; i < 8; i++) {
        const int n = base + row0 + i;
        if (n >= N_NODES) break;
        float4 o0, o1;
        o0.x = acc[i][0] + b0.x; o0.y = acc[i][1] + b0.y;
        o0.z = acc[i][2] + b0.z; o0.w = acc[i][3] + b0.w;
        o1.x = acc[i][4] + b1.x; o1.y = acc[i][5] + b1.y;
        o1.z = acc[i][6] + b1.z; o1.w = acc[i][7] + b1.w;
        *reinterpret_cast<float4*>(dst + (size_t)n * DIM + c)     = o0;
        *reinterpret_cast<float4*>(dst + (size_t)n * DIM + c + 4) = o1;
    }
}

// ---------------- per-destination attention + softmax + aggregation ----------------
// One block (128 threads) per destination node. Thread t owns feature dim t,
// head ht = t/16. Edge xl rows cached once in SMEM via cp.async.
__global__ __launch_bounds__(128, 4)
void agg_kernel(const float* __restrict__ x, const float* __restrict__ att,
                const float* __restrict__ bias, float* __restrict__ out)
{
    extern __shared__ float smem[];
    float* xs      = smem;                       // [MAXE][128]
    float* alpha_s = smem + MAXE * DIM;          // [MAXE][8]
    int*   s_src   = (int*)(alpha_s + MAXE * HEADS); // [MAXE]

    const int nid = blockIdx.x;
    const int t   = threadIdx.x;
    const int ht  = t >> 4;

    const int deg = g_deg[nid];
    const int st  = g_start[nid];
    const int nc  = (deg < MAXE) ? deg : MAXE;

    const float xr    = g_xr[(size_t)nid * DIM + t];
    const float att_t = att[t];

    if (t < nc) s_src[t] = g_src[st + t];
    __syncthreads();

    // Async gather of cached xl rows (4 rows per iteration, 16B per lane)
    {
        const int lane = t & 31;
        for (int r = t >> 5; r < nc; r += 4) {
            const float* gp = g_xl + (size_t)s_src[r] * DIM + lane * 4;
            uint32_t sa = (uint32_t)__cvta_generic_to_shared(&xs[r * DIM + lane * 4]);
            asm volatile("cp.async.cg.shared.global [%0], [%1], 16;\n" :: "r"(sa), "l"(gp));
        }
        asm volatile("cp.async.commit_group;\n");
        asm volatile("cp.async.wait_all;\n");
    }
    __syncthreads();

    // Pass 1: per-edge attention logit + running max per head
    float m = __int_as_float(0xff800000u);  // -inf
    for (int e = 0; e < nc; e++) {
        const float z  = xs[e * DIM + t] + xr;
        const float za = fmaxf(z, 0.f) + NEG_SLOPE * fminf(z, 0.f);
        float p = za * att_t;
        p += __shfl_xor_sync(0xffffffffu, p, 8);
        p += __shfl_xor_sync(0xffffffffu, p, 4);
        p += __shfl_xor_sync(0xffffffffu, p, 2);
        p += __shfl_xor_sync(0xffffffffu, p, 1);
        if ((t & 15) == 0) alpha_s[e * HEADS + ht] = p;
        m = fmaxf(m, p);
    }
    // Overflow edges (deg > MAXE): include in max (rare; Poisson(16))
    for (int e = nc; e < deg; e++) {
        const int src = g_src[st + e];
        const float z  = g_xl[(size_t)src * DIM + t] + xr;
        const float za = fmaxf(z, 0.f) + NEG_SLOPE * fminf(z, 0.f);
        float p = za * att_t;
        p += __shfl_xor_sync(0xffffffffu, p, 8);
        p += __shfl_xor_sync(0xffffffffu, p, 4);
        p += __shfl_xor_sync(0xffffffffu, p, 2);
        p += __shfl_xor_sync(0xffffffffu, p, 1);
        m = fmaxf(m, p);
    }
    __syncthreads();

    // Weight phase: exp once per (edge, head); partial denominator per lane
    float dsum = 0.f;
    for (int e = (t & 15); e < nc; e += 16) {
        const float w = __expf(alpha_s[e * HEADS + ht] - m);
        alpha_s[e * HEADS + ht] = w;
        dsum += w;
    }
    dsum += __shfl_xor_sync(0xffffffffu, dsum, 8);
    dsum += __shfl_xor_sync(0xffffffffu, dsum, 4);
    dsum += __shfl_xor_sync(0xffffffffu, dsum, 2);
    dsum += __shfl_xor_sync(0xffffffffu, dsum, 1);
    __syncthreads();

    // Pass 2: weighted aggregation from SMEM
    float acc = 0.f;
    for (int e = 0; e < nc; e++)
        acc = fmaf(xs[e * DIM + t], alpha_s[e * HEADS + ht], acc);

    float d = dsum;
    // Overflow edges: recompute and accumulate directly
    for (int e = nc; e < deg; e++) {
        const int src = g_src[st + e];
        const float xv = g_xl[(size_t)src * DIM + t];
        const float z  = xv + xr;
        const float za = fmaxf(z, 0.f) + NEG_SLOPE * fminf(z, 0.f);
        float p = za * att_t;
        p += __shfl_xor_sync(0xffffffffu, p, 8);
        p += __shfl_xor_sync(0xffffffffu, p, 4);
        p += __shfl_xor_sync(0xffffffffu, p, 2);
        p += __shfl_xor_sync(0xffffffffu, p, 1);
        const float w = __expf(p - m);
        d += w;
        acc = fmaf(xv, w, acc);
    }

    float o = acc / (d + 1e-16f);
    o += bias[t];
    o = fmaxf(o, 0.f);
    out[(size_t)nid * DIM + t] = x[(size_t)nid * DIM + t] + o;
}

// ---------------- launch ----------------
extern "C" void kernel_launch(void* const* d_in, const int* in_sizes, int n_in,
                              void* d_out, int out_size)
{
    const float* x    = (const float*)d_in[0];
    const int*   ei   = (const int*)d_in[1];
    const float* lng  = (const float*)d_in[2];
    const float* lnb  = (const float*)d_in[3];
    const float* Wl   = (const float*)d_in[4];
    const float* bl   = (const float*)d_in[5];
    const float* Wr   = (const float*)d_in[6];
    const float* br   = (const float*)d_in[7];
    const float* att  = (const float*)d_in[8];
    const float* bias = (const float*)d_in[9];
    float* out = (float*)d_out;

    const int GEMM_SMEM = (128 * 256 + MT * DIM) * 4;                       // 163840
    const int AGG_SMEM  = (MAXE * DIM + MAXE * HEADS) * 4 + MAXE * 4;       // 52608

    cudaFuncSetAttribute(ln_gemm_kernel, cudaFuncAttributeMaxDynamicSharedMemorySize, GEMM_SMEM);
    cudaFuncSetAttribute(agg_kernel,     cudaFuncAttributeMaxDynamicSharedMemorySize, AGG_SMEM);

    zero_kernel  <<<(N_NODES + 255) / 256, 256>>>();
    count_kernel <<<(E_EDGES + 255) / 256, 256>>>(ei);
    assign_kernel<<<(N_NODES + 255) / 256, 256>>>();
    fill_kernel  <<<(E_EDGES + 255) / 256, 256>>>(ei);
    ln_gemm_kernel<<<(N_NODES + MT - 1) / MT, 256, GEMM_SMEM>>>(x, lng, lnb, Wl, bl, Wr, br);
    agg_kernel    <<<N_NODES, 128, AGG_SMEM>>>(x, att, bias, out);
}

// round 2
// speedup vs baseline: 1.2387x; 1.2387x over previous
#include <cuda_runtime.h>
#include <cstdint>

#define N_NODES 50000
#define E_EDGES 800000
#define DIM 128
#define HEADS 8
#define NEG_SLOPE 0.15f
#define GROWS 128      // node rows per GEMM block
#define MAXE 96        // cached edges per destination in agg kernel

// ---------------- device scratch (no allocations allowed) ----------------
__device__ float g_xl[(size_t)N_NODES * DIM];
__device__ float g_xr[(size_t)N_NODES * DIM];
__device__ int   g_deg[N_NODES];
__device__ int   g_start[N_NODES];
__device__ int   g_cursor[N_NODES];
__device__ int   g_src[E_EDGES];
__device__ int   g_counter;

// ---------------- CSR build ----------------
__global__ void zero_kernel() {
    int i = blockIdx.x * blockDim.x + threadIdx.x;
    if (i < N_NODES) g_deg[i] = 0;
    if (i == 0) g_counter = 0;
}

__global__ void count_kernel(const int* __restrict__ ei) {
    int e = blockIdx.x * blockDim.x + threadIdx.x;
    if (e < E_EDGES) atomicAdd(&g_deg[ei[E_EDGES + e]], 1);
}

__global__ void assign_kernel() {
    int n = blockIdx.x * blockDim.x + threadIdx.x;
    if (n < N_NODES) {
        int d = g_deg[n];
        int s = atomicAdd(&g_counter, d);
        g_start[n]  = s;
        g_cursor[n] = s;
    }
}

__global__ void fill_kernel(const int* __restrict__ ei) {
    int e = blockIdx.x * blockDim.x + threadIdx.x;
    if (e < E_EDGES) {
        int s = ei[e];
        int d = ei[E_EDGES + e];
        int p = atomicAdd(&g_cursor[d], 1);
        g_src[p] = s;
    }
}

// ---------------- LayerNorm + dual GEMM (xl = h@Wl+bl, xr = h@Wr+br) ----------------
// Block: 512 threads, tile = 128 nodes x 256 output cols.
// Thread (warp, lane) computes rows warp*8..+7, cols lane*4..+3 (xl) and
// 128+lane*4..+3 (xr). Lane stride on weight float4 loads = 16B -> conflict-free.
// h-tile reads are warp-broadcast.
__global__ __launch_bounds__(512, 1)
void ln_gemm_kernel(const float* __restrict__ x,
                    const float* __restrict__ ln_g, const float* __restrict__ ln_b,
                    const float* __restrict__ Wl, const float* __restrict__ bl,
                    const float* __restrict__ Wr, const float* __restrict__ br)
{
    extern __shared__ float smem[];
    float* ws = smem;                  // [128][256]  (k-major, col 0..127 -> Wl, 128..255 -> Wr)
    float* hs = smem + 128 * 256;      // [128][128]

    const int tid  = threadIdx.x;
    const int base = blockIdx.x * GROWS;

    // Load concatenated weights into smem: threads 0..255 own col tid&255, 2 k-rows/iter
    {
        const int wc  = tid & 255;
        const int kr0 = tid >> 8;
        const float* wsrc = (wc < 128) ? Wl : Wr;
        const int col = wc & 127;
        #pragma unroll 8
        for (int k = kr0; k < 128; k += 2)
            ws[k * 256 + wc] = wsrc[k * 128 + col];
    }

    // LayerNorm: one warp per node (16 warps -> 8 iters for 128 rows), lane owns 4 dims
    const int warp = tid >> 5, lane = tid & 31;
    const float4 gv = reinterpret_cast<const float4*>(ln_g)[lane];
    const float4 bv = reinterpret_cast<const float4*>(ln_b)[lane];
    #pragma unroll 1
    for (int i = 0; i < 8; i++) {
        const int nl = i * 16 + warp;
        const int n  = base + nl;
        float4 v = make_float4(0.f, 0.f, 0.f, 0.f);
        if (n < N_NODES)
            v = reinterpret_cast<const float4*>(x + (size_t)n * DIM)[lane];
        float s = v.x + v.y + v.z + v.w;
        #pragma unroll
        for (int w = 16; w; w >>= 1) s += __shfl_xor_sync(0xffffffffu, s, w);
        const float mu = s * (1.0f / 128.0f);
        const float dx = v.x - mu, dy = v.y - mu, dz = v.z - mu, dw = v.w - mu;
        float q = dx * dx + dy * dy + dz * dz + dw * dw;
        #pragma unroll
        for (int w = 16; w; w >>= 1) q += __shfl_xor_sync(0xffffffffu, q, w);
        const float rs = rsqrtf(q * (1.0f / 128.0f) + 1e-5f);
        float4 h;
        h.x = dx * rs * gv.x + bv.x;
        h.y = dy * rs * gv.y + bv.y;
        h.z = dz * rs * gv.z + bv.z;
        h.w = dw * rs * gv.w + bv.w;
        reinterpret_cast<float4*>(hs + nl * DIM)[lane] = h;
    }
    __syncthreads();

    // Register-tiled GEMM: 8 rows x (4 xl cols + 4 xr cols) per thread
    const int row0 = warp * 8;
    const int cA   = lane * 4;
    float acc[8][8];
    #pragma unroll
    for (int i = 0; i < 8; i++)
        #pragma unroll
        for (int j = 0; j < 8; j++) acc[i][j] = 0.f;

    #pragma unroll 4
    for (int k = 0; k < 128; k++) {
        const float4 wa = *reinterpret_cast<const float4*>(&ws[k * 256 + cA]);        // Wl cols
        const float4 wb = *reinterpret_cast<const float4*>(&ws[k * 256 + 128 + cA]);  // Wr cols
        #pragma unroll
        for (int i = 0; i < 8; i++) {
            const float h = hs[(row0 + i) * DIM + k];   // warp-broadcast
            acc[i][0] = fmaf(h, wa.x, acc[i][0]);
            acc[i][1] = fmaf(h, wa.y, acc[i][1]);
            acc[i][2] = fmaf(h, wa.z, acc[i][2]);
            acc[i][3] = fmaf(h, wa.w, acc[i][3]);
            acc[i][4] = fmaf(h, wb.x, acc[i][4]);
            acc[i][5] = fmaf(h, wb.y, acc[i][5]);
            acc[i][6] = fmaf(h, wb.z, acc[i][6]);
            acc[i][7] = fmaf(h, wb.w, acc[i][7]);
        }
    }

    // Store with bias (coalesced float4 across lanes)
    const float4 b0 = *reinterpret_cast<const float4*>(&bl[cA]);
    const float4 b1 = *reinterpret_cast<const float4*>(&br[cA]);
    #pragma unroll
    for (int i = 0; i < 8; i++) {
        const int n = base + row0 + i;
        if (n >= N_NODES) break;
        float4 o0, o1;
        o0.x = acc[i][0] + b0.x; o0.y = acc[i][1] + b0.y;
        o0.z = acc[i][2] + b0.z; o0.w = acc[i][3] + b0.w;
        o1.x = acc[i][4] + b1.x; o1.y = acc[i][5] + b1.y;
        o1.z = acc[i][6] + b1.z; o1.w = acc[i][7] + b1.w;
        *reinterpret_cast<float4*>(g_xl + (size_t)n * DIM + cA) = o0;
        *reinterpret_cast<float4*>(g_xr + (size_t)n * DIM + cA) = o1;
    }
}

// ---------------- per-destination attention + softmax + aggregation ----------------
// One block (128 threads) per destination node. Thread t owns feature dim t,
// head ht = t/16. Edge xl rows cached once in SMEM via cp.async.
__global__ __launch_bounds__(128, 4)
void agg_kernel(const float* __restrict__ x, const float* __restrict__ att,
                const float* __restrict__ bias, float* __restrict__ out)
{
    extern __shared__ float smem[];
    float* xs      = smem;                       // [MAXE][128]
    float* alpha_s = smem + MAXE * DIM;          // [MAXE][8]
    int*   s_src   = (int*)(alpha_s + MAXE * HEADS); // [MAXE]

    const int nid = blockIdx.x;
    const int t   = threadIdx.x;
    const int ht  = t >> 4;

    const int deg = g_deg[nid];
    const int st  = g_start[nid];
    const int nc  = (deg < MAXE) ? deg : MAXE;

    const float xr    = g_xr[(size_t)nid * DIM + t];
    const float att_t = att[t];

    if (t < nc) s_src[t] = g_src[st + t];
    __syncthreads();

    // Async gather of cached xl rows (4 rows per iteration, 16B per lane)
    {
        const int lane = t & 31;
        for (int r = t >> 5; r < nc; r += 4) {
            const float* gp = g_xl + (size_t)s_src[r] * DIM + lane * 4;
            uint32_t sa = (uint32_t)__cvta_generic_to_shared(&xs[r * DIM + lane * 4]);
            asm volatile("cp.async.cg.shared.global [%0], [%1], 16;\n" :: "r"(sa), "l"(gp));
        }
        asm volatile("cp.async.commit_group;\n");
        asm volatile("cp.async.wait_all;\n");
    }
    __syncthreads();

    // Pass 1: per-edge attention logit + running max per head.
    // 2-edge unroll -> two independent SHFL chains in flight (halves latency exposure).
    float m = __int_as_float(0xff800000u);  // -inf
    int e = 0;
    for (; e + 1 < nc; e += 2) {
        const float z0 = xs[e * DIM + t] + xr;
        const float z1 = xs[(e + 1) * DIM + t] + xr;
        float p0 = (fmaxf(z0, 0.f) + NEG_SLOPE * fminf(z0, 0.f)) * att_t;
        float p1 = (fmaxf(z1, 0.f) + NEG_SLOPE * fminf(z1, 0.f)) * att_t;
        #pragma unroll
        for (int w = 8; w; w >>= 1) {
            p0 += __shfl_xor_sync(0xffffffffu, p0, w);
            p1 += __shfl_xor_sync(0xffffffffu, p1, w);
        }
        if ((t & 15) == 0) {
            alpha_s[e * HEADS + ht]       = p0;
            alpha_s[(e + 1) * HEADS + ht] = p1;
        }
        m = fmaxf(m, fmaxf(p0, p1));
    }
    if (e < nc) {
        const float z = xs[e * DIM + t] + xr;
        float p = (fmaxf(z, 0.f) + NEG_SLOPE * fminf(z, 0.f)) * att_t;
        #pragma unroll
        for (int w = 8; w; w >>= 1) p += __shfl_xor_sync(0xffffffffu, p, w);
        if ((t & 15) == 0) alpha_s[e * HEADS + ht] = p;
        m = fmaxf(m, p);
    }
    // Overflow edges (deg > MAXE): include in max (rare; Poisson(16))
    for (int eo = nc; eo < deg; eo++) {
        const int src = g_src[st + eo];
        const float z = g_xl[(size_t)src * DIM + t] + xr;
        float p = (fmaxf(z, 0.f) + NEG_SLOPE * fminf(z, 0.f)) * att_t;
        #pragma unroll
        for (int w = 8; w; w >>= 1) p += __shfl_xor_sync(0xffffffffu, p, w);
        m = fmaxf(m, p);
    }
    __syncthreads();

    // Weight phase: exp once per (edge, head); partial denominator per lane
    float dsum = 0.f;
    for (int e2 = (t & 15); e2 < nc; e2 += 16) {
        const float w = __expf(alpha_s[e2 * HEADS + ht] - m);
        alpha_s[e2 * HEADS + ht] = w;
        dsum += w;
    }
    #pragma unroll
    for (int w = 8; w; w >>= 1) dsum += __shfl_xor_sync(0xffffffffu, dsum, w);
    __syncthreads();

    // Pass 2: weighted aggregation from SMEM
    float acc = 0.f;
    for (int e2 = 0; e2 < nc; e2++)
        acc = fmaf(xs[e2 * DIM + t], alpha_s[e2 * HEADS + ht], acc);

    float d = dsum;
    // Overflow edges: recompute and accumulate directly
    for (int eo = nc; eo < deg; eo++) {
        const int src = g_src[st + eo];
        const float xv = g_xl[(size_t)src * DIM + t];
        const float z  = xv + xr;
        float p = (fmaxf(z, 0.f) + NEG_SLOPE * fminf(z, 0.f)) * att_t;
        #pragma unroll
        for (int w = 8; w; w >>= 1) p += __shfl_xor_sync(0xffffffffu, p, w);
        const float wgt = __expf(p - m);
        d += wgt;
        acc = fmaf(xv, wgt, acc);
    }

    float o = acc / (d + 1e-16f);
    o += bias[t];
    o = fmaxf(o, 0.f);
    out[(size_t)nid * DIM + t] = x[(size_t)nid * DIM + t] + o;
}

// ---------------- launch ----------------
extern "C" void kernel_launch(void* const* d_in, const int* in_sizes, int n_in,
                              void* d_out, int out_size)
{
    const float* x    = (const float*)d_in[0];
    const int*   ei   = (const int*)d_in[1];
    const float* lng  = (const float*)d_in[2];
    const float* lnb  = (const float*)d_in[3];
    const float* Wl   = (const float*)d_in[4];
    const float* bl   = (const float*)d_in[5];
    const float* Wr   = (const float*)d_in[6];
    const float* br   = (const float*)d_in[7];
    const float* att  = (const float*)d_in[8];
    const float* bias = (const float*)d_in[9];
    float* out = (float*)d_out;

    const int GEMM_SMEM = (128 * 256 + GROWS * DIM) * 4;                    // 196608
    const int AGG_SMEM  = (MAXE * DIM + MAXE * HEADS) * 4 + MAXE * 4;       // 52608

    cudaFuncSetAttribute(ln_gemm_kernel, cudaFuncAttributeMaxDynamicSharedMemorySize, GEMM_SMEM);
    cudaFuncSetAttribute(agg_kernel,     cudaFuncAttributeMaxDynamicSharedMemorySize, AGG_SMEM);

    zero_kernel  <<<(N_NODES + 255) / 256, 256>>>();
    count_kernel <<<(E_EDGES + 255) / 256, 256>>>(ei);
    assign_kernel<<<(N_NODES + 255) / 256, 256>>>();
    fill_kernel  <<<(E_EDGES + 255) / 256, 256>>>(ei);
    ln_gemm_kernel<<<(N_NODES + GROWS - 1) / GROWS, 512, GEMM_SMEM>>>(x, lng, lnb, Wl, bl, Wr, br);
    agg_kernel    <<<N_NODES, 128, AGG_SMEM>>>(x, att, bias, out);
}

// round 3
// speedup vs baseline: 2.6874x; 2.1695x over previous
#include <cuda_runtime.h>
#include <cstdint>

#define N_NODES 50000
#define E_EDGES 800000
#define DIM 128
#define HEADS 8
#define NEG_SLOPE 0.15f
#define GROWS 128      // node rows per GEMM block

// ---------------- device scratch (no allocations allowed) ----------------
__device__ float g_xl[(size_t)N_NODES * DIM];
__device__ float g_xr[(size_t)N_NODES * DIM];
__device__ int   g_deg[N_NODES];
__device__ int   g_start[N_NODES];
__device__ int   g_cursor[N_NODES];
__device__ int   g_src[E_EDGES];
__device__ int   g_counter;

// ---------------- CSR build ----------------
__global__ void zero_kernel() {
    int i = blockIdx.x * blockDim.x + threadIdx.x;
    if (i < N_NODES) g_deg[i] = 0;
    if (i == 0) g_counter = 0;
}

__global__ void count_kernel(const int* __restrict__ ei) {
    int e = blockIdx.x * blockDim.x + threadIdx.x;
    if (e < E_EDGES) atomicAdd(&g_deg[ei[E_EDGES + e]], 1);
}

__global__ void assign_kernel() {
    int n = blockIdx.x * blockDim.x + threadIdx.x;
    if (n < N_NODES) {
        int d = g_deg[n];
        int s = atomicAdd(&g_counter, d);
        g_start[n]  = s;
        g_cursor[n] = s;
    }
}

__global__ void fill_kernel(const int* __restrict__ ei) {
    int e = blockIdx.x * blockDim.x + threadIdx.x;
    if (e < E_EDGES) {
        int s = ei[e];
        int d = ei[E_EDGES + e];
        int p = atomicAdd(&g_cursor[d], 1);
        g_src[p] = s;
    }
}

// ---------------- LayerNorm + dual GEMM (xl = h@Wl+bl, xr = h@Wr+br) ----------------
__global__ __launch_bounds__(512, 1)
void ln_gemm_kernel(const float* __restrict__ x,
                    const float* __restrict__ ln_g, const float* __restrict__ ln_b,
                    const float* __restrict__ Wl, const float* __restrict__ bl,
                    const float* __restrict__ Wr, const float* __restrict__ br)
{
    extern __shared__ float smem[];
    float* ws = smem;                  // [128][256]  (k-major, col 0..127 -> Wl, 128..255 -> Wr)
    float* hs = smem + 128 * 256;      // [128][128]

    const int tid  = threadIdx.x;
    const int base = blockIdx.x * GROWS;

    // Load concatenated weights into smem
    {
        const int wc  = tid & 255;
        const int kr0 = tid >> 8;
        const float* wsrc = (wc < 128) ? Wl : Wr;
        const int col = wc & 127;
        #pragma unroll 8
        for (int k = kr0; k < 128; k += 2)
            ws[k * 256 + wc] = wsrc[k * 128 + col];
    }

    // LayerNorm: one warp per node, lane owns 4 dims
    const int warp = tid >> 5, lane = tid & 31;
    const float4 gv = reinterpret_cast<const float4*>(ln_g)[lane];
    const float4 bv = reinterpret_cast<const float4*>(ln_b)[lane];
    #pragma unroll 1
    for (int i = 0; i < 8; i++) {
        const int nl = i * 16 + warp;
        const int n  = base + nl;
        float4 v = make_float4(0.f, 0.f, 0.f, 0.f);
        if (n < N_NODES)
            v = reinterpret_cast<const float4*>(x + (size_t)n * DIM)[lane];
        float s = v.x + v.y + v.z + v.w;
        #pragma unroll
        for (int w = 16; w; w >>= 1) s += __shfl_xor_sync(0xffffffffu, s, w);
        const float mu = s * (1.0f / 128.0f);
        const float dx = v.x - mu, dy = v.y - mu, dz = v.z - mu, dw = v.w - mu;
        float q = dx * dx + dy * dy + dz * dz + dw * dw;
        #pragma unroll
        for (int w = 16; w; w >>= 1) q += __shfl_xor_sync(0xffffffffu, q, w);
        const float rs = rsqrtf(q * (1.0f / 128.0f) + 1e-5f);
        float4 h;
        h.x = dx * rs * gv.x + bv.x;
        h.y = dy * rs * gv.y + bv.y;
        h.z = dz * rs * gv.z + bv.z;
        h.w = dw * rs * gv.w + bv.w;
        reinterpret_cast<float4*>(hs + nl * DIM)[lane] = h;
    }
    __syncthreads();

    // Register-tiled GEMM: 8 rows x (4 xl cols + 4 xr cols) per thread
    const int row0 = warp * 8;
    const int cA   = lane * 4;
    float acc[8][8];
    #pragma unroll
    for (int i = 0; i < 8; i++)
        #pragma unroll
        for (int j = 0; j < 8; j++) acc[i][j] = 0.f;

    #pragma unroll 4
    for (int k = 0; k < 128; k++) {
        const float4 wa = *reinterpret_cast<const float4*>(&ws[k * 256 + cA]);
        const float4 wb = *reinterpret_cast<const float4*>(&ws[k * 256 + 128 + cA]);
        #pragma unroll
        for (int i = 0; i < 8; i++) {
            const float h = hs[(row0 + i) * DIM + k];   // warp-broadcast
            acc[i][0] = fmaf(h, wa.x, acc[i][0]);
            acc[i][1] = fmaf(h, wa.y, acc[i][1]);
            acc[i][2] = fmaf(h, wa.z, acc[i][2]);
            acc[i][3] = fmaf(h, wa.w, acc[i][3]);
            acc[i][4] = fmaf(h, wb.x, acc[i][4]);
            acc[i][5] = fmaf(h, wb.y, acc[i][5]);
            acc[i][6] = fmaf(h, wb.z, acc[i][6]);
            acc[i][7] = fmaf(h, wb.w, acc[i][7]);
        }
    }

    const float4 b0 = *reinterpret_cast<const float4*>(&bl[cA]);
    const float4 b1 = *reinterpret_cast<const float4*>(&br[cA]);
    #pragma unroll
    for (int i = 0; i < 8; i++) {
        const int n = base + row0 + i;
        if (n >= N_NODES) break;
        float4 o0, o1;
        o0.x = acc[i][0] + b0.x; o0.y = acc[i][1] + b0.y;
        o0.z = acc[i][2] + b0.z; o0.w = acc[i][3] + b0.w;
        o1.x = acc[i][4] + b1.x; o1.y = acc[i][5] + b1.y;
        o1.z = acc[i][6] + b1.z; o1.w = acc[i][7] + b1.w;
        *reinterpret_cast<float4*>(g_xl + (size_t)n * DIM + cA) = o0;
        *reinterpret_cast<float4*>(g_xr + (size_t)n * DIM + cA) = o1;
    }
}

// ---------------- warp-per-destination online-softmax aggregation ----------------
// One warp per destination node. Lane owns dims lane*4..lane*4+3; head = lane/4
// (4 lanes per head -> 2-shfl logit reduction). Flash-style online softmax:
// xl[src] rows are read from L2 exactly once, no SMEM, no block syncs.
__global__ __launch_bounds__(256)
void agg_kernel(const float* __restrict__ x, const float* __restrict__ att,
                const float* __restrict__ bias, float* __restrict__ out)
{
    const int warp = threadIdx.x >> 5;
    const int lane = threadIdx.x & 31;
    const int nid  = blockIdx.x * 8 + warp;
    if (nid >= N_NODES) return;

    const int deg = g_deg[nid];
    const int st  = g_start[nid];

    const float4 xr4  = *reinterpret_cast<const float4*>(g_xr + (size_t)nid * DIM + lane * 4);
    const float4 att4 = reinterpret_cast<const float4*>(att)[lane];

    float  m = __int_as_float(0xff800000u);   // -inf
    float  d = 0.f;
    float4 acc = make_float4(0.f, 0.f, 0.f, 0.f);

    for (int base = 0; base < deg; base += 32) {
        const int cnt = min(32, deg - base);
        const int my_src = (lane < cnt) ? g_src[st + base + lane] : 0;

        int e = 0;
        for (; e + 1 < cnt; e += 2) {
            const int s0 = __shfl_sync(0xffffffffu, my_src, e);
            const int s1 = __shfl_sync(0xffffffffu, my_src, e + 1);
            const float4 v0 = *reinterpret_cast<const float4*>(g_xl + (size_t)s0 * DIM + lane * 4);
            const float4 v1 = *reinterpret_cast<const float4*>(g_xl + (size_t)s1 * DIM + lane * 4);

            float z, p0, p1;
            z  = v0.x + xr4.x; p0  = (fmaxf(z,0.f) + NEG_SLOPE*fminf(z,0.f)) * att4.x;
            z  = v0.y + xr4.y; p0 += (fmaxf(z,0.f) + NEG_SLOPE*fminf(z,0.f)) * att4.y;
            z  = v0.z + xr4.z; p0 += (fmaxf(z,0.f) + NEG_SLOPE*fminf(z,0.f)) * att4.z;
            z  = v0.w + xr4.w; p0 += (fmaxf(z,0.f) + NEG_SLOPE*fminf(z,0.f)) * att4.w;
            z  = v1.x + xr4.x; p1  = (fmaxf(z,0.f) + NEG_SLOPE*fminf(z,0.f)) * att4.x;
            z  = v1.y + xr4.y; p1 += (fmaxf(z,0.f) + NEG_SLOPE*fminf(z,0.f)) * att4.y;
            z  = v1.z + xr4.z; p1 += (fmaxf(z,0.f) + NEG_SLOPE*fminf(z,0.f)) * att4.z;
            z  = v1.w + xr4.w; p1 += (fmaxf(z,0.f) + NEG_SLOPE*fminf(z,0.f)) * att4.w;

            p0 += __shfl_xor_sync(0xffffffffu, p0, 1);
            p1 += __shfl_xor_sync(0xffffffffu, p1, 1);
            p0 += __shfl_xor_sync(0xffffffffu, p0, 2);
            p1 += __shfl_xor_sync(0xffffffffu, p1, 2);

            const float mn = fmaxf(m, fmaxf(p0, p1));
            const float em = __expf(m - mn);
            const float w0 = __expf(p0 - mn);
            const float w1 = __expf(p1 - mn);
            d = d * em + w0 + w1;
            acc.x = acc.x * em + v0.x * w0 + v1.x * w1;
            acc.y = acc.y * em + v0.y * w0 + v1.y * w1;
            acc.z = acc.z * em + v0.z * w0 + v1.z * w1;
            acc.w = acc.w * em + v0.w * w0 + v1.w * w1;
            m = mn;
        }
        if (e < cnt) {
            const int s0 = __shfl_sync(0xffffffffu, my_src, e);
            const float4 v0 = *reinterpret_cast<const float4*>(g_xl + (size_t)s0 * DIM + lane * 4);
            float z, p0;
            z  = v0.x + xr4.x; p0  = (fmaxf(z,0.f) + NEG_SLOPE*fminf(z,0.f)) * att4.x;
            z  = v0.y + xr4.y; p0 += (fmaxf(z,0.f) + NEG_SLOPE*fminf(z,0.f)) * att4.y;
            z  = v0.z + xr4.z; p0 += (fmaxf(z,0.f) + NEG_SLOPE*fminf(z,0.f)) * att4.z;
            z  = v0.w + xr4.w; p0 += (fmaxf(z,0.f) + NEG_SLOPE*fminf(z,0.f)) * att4.w;
            p0 += __shfl_xor_sync(0xffffffffu, p0, 1);
            p0 += __shfl_xor_sync(0xffffffffu, p0, 2);

            const float mn = fmaxf(m, p0);
            const float em = __expf(m - mn);
            const float w0 = __expf(p0 - mn);
            d = d * em + w0;
            acc.x = acc.x * em + v0.x * w0;
            acc.y = acc.y * em + v0.y * w0;
            acc.z = acc.z * em + v0.z * w0;
            acc.w = acc.w * em + v0.w * w0;
            m = mn;
        }
    }

    const float inv = 1.0f / (d + 1e-16f);
    const float4 bias4 = reinterpret_cast<const float4*>(bias)[lane];
    const float4 x4 = *reinterpret_cast<const float4*>(x + (size_t)nid * DIM + lane * 4);
    float4 o;
    o.x = x4.x + fmaxf(acc.x * inv + bias4.x, 0.f);
    o.y = x4.y + fmaxf(acc.y * inv + bias4.y, 0.f);
    o.z = x4.z + fmaxf(acc.z * inv + bias4.z, 0.f);
    o.w = x4.w + fmaxf(acc.w * inv + bias4.w, 0.f);
    *reinterpret_cast<float4*>(out + (size_t)nid * DIM + lane * 4) = o;
}

// ---------------- launch ----------------
extern "C" void kernel_launch(void* const* d_in, const int* in_sizes, int n_in,
                              void* d_out, int out_size)
{
    const float* x    = (const float*)d_in[0];
    const int*   ei   = (const int*)d_in[1];
    const float* lng  = (const float*)d_in[2];
    const float* lnb  = (const float*)d_in[3];
    const float* Wl   = (const float*)d_in[4];
    const float* bl   = (const float*)d_in[5];
    const float* Wr   = (const float*)d_in[6];
    const float* br   = (const float*)d_in[7];
    const float* att  = (const float*)d_in[8];
    const float* bias = (const float*)d_in[9];
    float* out = (float*)d_out;

    const int GEMM_SMEM = (128 * 256 + GROWS * DIM) * 4;   // 196608
    cudaFuncSetAttribute(ln_gemm_kernel, cudaFuncAttributeMaxDynamicSharedMemorySize, GEMM_SMEM);

    zero_kernel  <<<(N_NODES + 255) / 256, 256>>>();
    count_kernel <<<(E_EDGES + 255) / 256, 256>>>(ei);
    assign_kernel<<<(N_NODES + 255) / 256, 256>>>();
    fill_kernel  <<<(E_EDGES + 255) / 256, 256>>>(ei);
    ln_gemm_kernel<<<(N_NODES + GROWS - 1) / GROWS, 512, GEMM_SMEM>>>(x, lng, lnb, Wl, bl, Wr, br);
    agg_kernel    <<<(N_NODES + 7) / 8, 256>>>(x, att, bias, out);
}

// round 5
// speedup vs baseline: 3.9327x; 1.4634x over previous
#include <cuda_runtime.h>
#include <cuda_bf16.h>
#include <cstdint>

#define N_NODES 50000
#define E_EDGES 800000
#define DIM 128
#define NEG_SLOPE 0.15f
#define GROWS 128
#define NTILES ((N_NODES + GROWS - 1) / GROWS)
#define LDA 136        // padded row length (bf16 elems) -> conflict-free ldmatrix

// ---------------- device scratch (no allocations allowed) ----------------
__device__ float g_xl[(size_t)N_NODES * DIM];
__device__ float g_xr[(size_t)N_NODES * DIM];
__device__ int   g_deg[N_NODES];
__device__ int   g_start[N_NODES];
__device__ int   g_cursor[N_NODES];
__device__ int   g_src[E_EDGES];
__device__ int   g_counter;
// pre-split B images, padded row-major [256][LDA]: row n = output col, col k
__device__ __align__(16) __nv_bfloat16 g_Bhi[256 * LDA];
__device__ __align__(16) __nv_bfloat16 g_Blo[256 * LDA];

// ---------------- CSR build ----------------
__global__ void zero_kernel() {
    int i = blockIdx.x * blockDim.x + threadIdx.x;
    if (i < N_NODES) g_deg[i] = 0;
    if (i == 0) g_counter = 0;
}
__global__ void count_kernel(const int* __restrict__ ei) {
    int e = blockIdx.x * blockDim.x + threadIdx.x;
    if (e < E_EDGES) atomicAdd(&g_deg[ei[E_EDGES + e]], 1);
}
__global__ void assign_kernel() {
    int n = blockIdx.x * blockDim.x + threadIdx.x;
    if (n < N_NODES) {
        int d = g_deg[n];
        int s = atomicAdd(&g_counter, d);
        g_start[n]  = s;
        g_cursor[n] = s;
    }
}
__global__ void fill_kernel(const int* __restrict__ ei) {
    int e = blockIdx.x * blockDim.x + threadIdx.x;
    if (e < E_EDGES) {
        int s = ei[e];
        int d = ei[E_EDGES + e];
        int p = atomicAdd(&g_cursor[d], 1);
        g_src[p] = s;
    }
}

// ---------------- one-time W split into padded B images ----------------
__global__ void prep_b_kernel(const float* __restrict__ Wl, const float* __restrict__ Wr) {
    int idx = blockIdx.x * blockDim.x + threadIdx.x;   // 0 .. 256*128-1
    if (idx >= 256 * 128) return;
    int n = idx >> 7;          // output column (0..255); <128 -> Wl
    int k = idx & 127;
    float v = (n < 128) ? Wl[k * 128 + n] : Wr[k * 128 + (n - 128)];
    __nv_bfloat16 hi = __float2bfloat16(v);
    __nv_bfloat16 lo = __float2bfloat16(v - __bfloat162float(hi));
    g_Bhi[n * LDA + k] = hi;
    g_Blo[n * LDA + k] = lo;
}

// ---------------- mma helpers (baseline PTX: sm_75/80 features) ----------------
__device__ __forceinline__ uint32_t smem_u32(const void* p) {
    uint32_t a;
    asm("{ .reg .u64 t; cvta.to.shared.u64 t, %1; cvt.u32.u64 %0, t; }" : "=r"(a) : "l"(p));
    return a;
}
__device__ __forceinline__ void ldsm_x4(uint32_t* r, uint32_t addr) {
    asm volatile("ldmatrix.sync.aligned.m8n8.x4.shared.b16 {%0,%1,%2,%3}, [%4];"
                 : "=r"(r[0]), "=r"(r[1]), "=r"(r[2]), "=r"(r[3]) : "r"(addr));
}
__device__ __forceinline__ void mma_bf16(float* d, const uint32_t* a, const uint32_t* b) {
    asm volatile(
        "mma.sync.aligned.m16n8k16.row.col.f32.bf16.bf16.f32 "
        "{%0,%1,%2,%3}, {%4,%5,%6,%7}, {%8,%9}, {%0,%1,%2,%3};"
        : "+f"(d[0]), "+f"(d[1]), "+f"(d[2]), "+f"(d[3])
        : "r"(a[0]), "r"(a[1]), "r"(a[2]), "r"(a[3]), "r"(b[0]), "r"(b[1]));
}

// SMEM layout (bytes): A images [128][LDA] bf16, B images [256][LDA] bf16
#define SM_AHI  0
#define SM_ALO  (128 * LDA * 2)                 // 34816
#define SM_BHI  (SM_ALO + 128 * LDA * 2)        // 69632
#define SM_BLO  (SM_BHI + 256 * LDA * 2)        // 139264
#define SM_TOTAL (SM_BLO + 256 * LDA * 2)       // 208896

// ---------------- LayerNorm + dual GEMM via mma.sync bf16 split ----------------
// 512 threads / 16 warps. Tile 128 rows x 256 cols (xl||xr), K=128.
// Warp (wm = wid&3, wn = wid>>2) computes rows wm*32..+31, cols wn*64..+63.
// D = Ah*Bh + Ah*Bl + Al*Bh, fp32 accumulate in registers.
__global__ __launch_bounds__(512, 1)
void ln_gemm_kernel(const float* __restrict__ x,
                    const float* __restrict__ ln_g, const float* __restrict__ ln_b,
                    const float* __restrict__ bl, const float* __restrict__ br)
{
    extern __shared__ char smem[];
    const uint32_t sb = smem_u32(smem);
    const int tid  = threadIdx.x;
    const int wid  = tid >> 5;
    const int lane = tid & 31;
    const int base = blockIdx.x * GROWS;

    // Copy pre-split B images (padded layout) into smem, 16B chunks
    {
        const uint4* gh = reinterpret_cast<const uint4*>(g_Bhi);
        const uint4* gl = reinterpret_cast<const uint4*>(g_Blo);
        uint4* sh = reinterpret_cast<uint4*>(smem + SM_BHI);
        uint4* sl = reinterpret_cast<uint4*>(smem + SM_BLO);
        #pragma unroll 2
        for (int i = tid; i < 256 * LDA * 2 / 16; i += 512) {
            sh[i] = gh[i];
            sl[i] = gl[i];
        }
    }

    // LayerNorm -> split bf16 -> padded A images. One warp per node row.
    {
        const float4 gv = reinterpret_cast<const float4*>(ln_g)[lane];
        const float4 bv = reinterpret_cast<const float4*>(ln_b)[lane];
        #pragma unroll 1
        for (int i = 0; i < 8; i++) {
            const int nl = i * 16 + wid;
            const int n  = base + nl;
            float4 v = make_float4(0.f, 0.f, 0.f, 0.f);
            if (n < N_NODES)
                v = reinterpret_cast<const float4*>(x + (size_t)n * DIM)[lane];
            float s = v.x + v.y + v.z + v.w;
            #pragma unroll
            for (int w = 16; w; w >>= 1) s += __shfl_xor_sync(0xffffffffu, s, w);
            const float mu = s * (1.0f / 128.0f);
            const float dx = v.x - mu, dy = v.y - mu, dz = v.z - mu, dw = v.w - mu;
            float q = dx * dx + dy * dy + dz * dz + dw * dw;
            #pragma unroll
            for (int w = 16; w; w >>= 1) q += __shfl_xor_sync(0xffffffffu, q, w);
            const float rs = rsqrtf(q * (1.0f / 128.0f) + 1e-5f);
            float h[4];
            h[0] = dx * rs * gv.x + bv.x;
            h[1] = dy * rs * gv.y + bv.y;
            h[2] = dz * rs * gv.z + bv.z;
            h[3] = dw * rs * gv.w + bv.w;
            uint32_t phi[2], plo[2];
            #pragma unroll
            for (int j = 0; j < 2; j++) {
                __nv_bfloat16 h0 = __float2bfloat16(h[2 * j]);
                __nv_bfloat16 h1 = __float2bfloat16(h[2 * j + 1]);
                __nv_bfloat16 l0 = __float2bfloat16(h[2 * j]     - __bfloat162float(h0));
                __nv_bfloat16 l1 = __float2bfloat16(h[2 * j + 1] - __bfloat162float(h1));
                phi[j] = (uint32_t)__bfloat16_as_ushort(h1) << 16 | __bfloat16_as_ushort(h0);
                plo[j] = (uint32_t)__bfloat16_as_ushort(l1) << 16 | __bfloat16_as_ushort(l0);
            }
            const uint32_t off = (uint32_t)(nl * LDA + lane * 4) * 2;   // bytes, 8B aligned
            *reinterpret_cast<uint2*>(smem + SM_AHI + off) = make_uint2(phi[0], phi[1]);
            *reinterpret_cast<uint2*>(smem + SM_ALO + off) = make_uint2(plo[0], plo[1]);
        }
    }
    __syncthreads();

    // ---- MMA mainloop ----
    const int wm = wid & 3;
    const int wn = wid >> 2;

    // ldmatrix per-lane addresses:
    // A (x4: m0=rows0-7@k0, m1=rows8-15@k0, m2=rows0-7@k8, m3=rows8-15@k8):
    const uint32_t aRow = (uint32_t)(wm * 32 + (lane & 15));
    const uint32_t aK   = (uint32_t)((lane >> 4) * 8);
    const uint32_t aHi  = sb + SM_AHI + (aRow * LDA + aK) * 2;
    const uint32_t aLo  = sb + SM_ALO + (aRow * LDA + aK) * 2;
    // B (x4 covers 2 n-blocks: m0=n0-7@k0, m1=n0-7@k8, m2=n8-15@k0, m3=n8-15@k8):
    const uint32_t bRow = (uint32_t)(wn * 64 + (lane & 7) + ((lane >> 4) & 1) * 8);
    const uint32_t bK   = (uint32_t)(((lane >> 3) & 1) * 8);
    const uint32_t bHi  = sb + SM_BHI + (bRow * LDA + bK) * 2;
    const uint32_t bLo  = sb + SM_BLO + (bRow * LDA + bK) * 2;

    float d[2][8][4];
    #pragma unroll
    for (int mf = 0; mf < 2; mf++)
        #pragma unroll
        for (int nf = 0; nf < 8; nf++)
            #pragma unroll
            for (int j = 0; j < 4; j++) d[mf][nf][j] = 0.f;

    #pragma unroll 1
    for (int ks = 0; ks < 8; ks++) {
        const uint32_t kb = (uint32_t)ks * 32;   // 16 elems * 2B
        uint32_t ah[2][4], al[2][4], bh[8][2], blo[8][2];
        #pragma unroll
        for (int mf = 0; mf < 2; mf++) {
            ldsm_x4(ah[mf], aHi + (uint32_t)(mf * 16 * LDA * 2) + kb);
            ldsm_x4(al[mf], aLo + (uint32_t)(mf * 16 * LDA * 2) + kb);
        }
        #pragma unroll
        for (int p = 0; p < 4; p++) {
            uint32_t r[4];
            ldsm_x4(r, bHi + (uint32_t)(p * 16 * LDA * 2) + kb);
            bh[2 * p][0] = r[0]; bh[2 * p][1] = r[1];
            bh[2 * p + 1][0] = r[2]; bh[2 * p + 1][1] = r[3];
            ldsm_x4(r, bLo + (uint32_t)(p * 16 * LDA * 2) + kb);
            blo[2 * p][0] = r[0]; blo[2 * p][1] = r[1];
            blo[2 * p + 1][0] = r[2]; blo[2 * p + 1][1] = r[3];
        }
        #pragma unroll
        for (int mf = 0; mf < 2; mf++)
            #pragma unroll
            for (int nf = 0; nf < 8; nf++) {
                mma_bf16(d[mf][nf], ah[mf], bh[nf]);
                mma_bf16(d[mf][nf], ah[mf], blo[nf]);
                mma_bf16(d[mf][nf], al[mf], bh[nf]);
            }
    }

    // ---- Epilogue: fragment -> g_xl / g_xr with bias ----
    {
        const int half   = wn >> 1;                 // 0 -> xl, 1 -> xr
        const int cbase  = (wn & 1) * 64;           // local col within 128-half
        const float* bb  = half ? br : bl;
        float*       dst = half ? g_xr : g_xl;
        #pragma unroll
        for (int mf = 0; mf < 2; mf++) {
            const int r0 = wm * 32 + mf * 16 + (lane >> 2);
            #pragma unroll
            for (int nf = 0; nf < 8; nf++) {
                const int c = cbase + nf * 8 + (lane & 3) * 2;
                const float2 bv = *reinterpret_cast<const float2*>(&bb[c]);
                const int n0 = base + r0;
                const int n1 = n0 + 8;
                if (n0 < N_NODES) {
                    float2 o = make_float2(d[mf][nf][0] + bv.x, d[mf][nf][1] + bv.y);
                    *reinterpret_cast<float2*>(dst + (size_t)n0 * DIM + c) = o;
                }
                if (n1 < N_NODES) {
                    float2 o = make_float2(d[mf][nf][2] + bv.x, d[mf][nf][3] + bv.y);
                    *reinterpret_cast<float2*>(dst + (size_t)n1 * DIM + c) = o;
                }
            }
        }
    }
}

// ---------------- warp-per-destination online-softmax aggregation ----------------
__global__ __launch_bounds__(256)
void agg_kernel(const float* __restrict__ x, const float* __restrict__ att,
                const float* __restrict__ bias, float* __restrict__ out)
{
    const int warp = threadIdx.x >> 5;
    const int lane = threadIdx.x & 31;
    const int nid  = blockIdx.x * 8 + warp;
    if (nid >= N_NODES) return;

    const int deg = g_deg[nid];
    const int st  = g_start[nid];

    const float4 xr4  = *reinterpret_cast<const float4*>(g_xr + (size_t)nid * DIM + lane * 4);
    const float4 att4 = reinterpret_cast<const float4*>(att)[lane];

    float  m = __int_as_float(0xff800000u);
    float  d = 0.f;
    float4 acc = make_float4(0.f, 0.f, 0.f, 0.f);

    for (int base = 0; base < deg; base += 32) {
        const int cnt = min(32, deg - base);
        const int my_src = (lane < cnt) ? g_src[st + base + lane] : 0;

        int e = 0;
        for (; e + 1 < cnt; e += 2) {
            const int s0 = __shfl_sync(0xffffffffu, my_src, e);
            const int s1 = __shfl_sync(0xffffffffu, my_src, e + 1);
            const float4 v0 = *reinterpret_cast<const float4*>(g_xl + (size_t)s0 * DIM + lane * 4);
            const float4 v1 = *reinterpret_cast<const float4*>(g_xl + (size_t)s1 * DIM + lane * 4);

            float z, p0, p1;
            z  = v0.x + xr4.x; p0  = (fmaxf(z,0.f) + NEG_SLOPE*fminf(z,0.f)) * att4.x;
            z  = v0.y + xr4.y; p0 += (fmaxf(z,0.f) + NEG_SLOPE*fminf(z,0.f)) * att4.y;
            z  = v0.z + xr4.z; p0 += (fmaxf(z,0.f) + NEG_SLOPE*fminf(z,0.f)) * att4.z;
            z  = v0.w + xr4.w; p0 += (fmaxf(z,0.f) + NEG_SLOPE*fminf(z,0.f)) * att4.w;
            z  = v1.x + xr4.x; p1  = (fmaxf(z,0.f) + NEG_SLOPE*fminf(z,0.f)) * att4.x;
            z  = v1.y + xr4.y; p1 += (fmaxf(z,0.f) + NEG_SLOPE*fminf(z,0.f)) * att4.y;
            z  = v1.z + xr4.z; p1 += (fmaxf(z,0.f) + NEG_SLOPE*fminf(z,0.f)) * att4.z;
            z  = v1.w + xr4.w; p1 += (fmaxf(z,0.f) + NEG_SLOPE*fminf(z,0.f)) * att4.w;

            p0 += __shfl_xor_sync(0xffffffffu, p0, 1);
            p1 += __shfl_xor_sync(0xffffffffu, p1, 1);
            p0 += __shfl_xor_sync(0xffffffffu, p0, 2);
            p1 += __shfl_xor_sync(0xffffffffu, p1, 2);

            const float mn = fmaxf(m, fmaxf(p0, p1));
            const float em = __expf(m - mn);
            const float w0 = __expf(p0 - mn);
            const float w1 = __expf(p1 - mn);
            d = d * em + w0 + w1;
            acc.x = acc.x * em + v0.x * w0 + v1.x * w1;
            acc.y = acc.y * em + v0.y * w0 + v1.y * w1;
            acc.z = acc.z * em + v0.z * w0 + v1.z * w1;
            acc.w = acc.w * em + v0.w * w0 + v1.w * w1;
            m = mn;
        }
        if (e < cnt) {
            const int s0 = __shfl_sync(0xffffffffu, my_src, e);
            const float4 v0 = *reinterpret_cast<const float4*>(g_xl + (size_t)s0 * DIM + lane * 4);
            float z, p0;
            z  = v0.x + xr4.x; p0  = (fmaxf(z,0.f) + NEG_SLOPE*fminf(z,0.f)) * att4.x;
            z  = v0.y + xr4.y; p0 += (fmaxf(z,0.f) + NEG_SLOPE*fminf(z,0.f)) * att4.y;
            z  = v0.z + xr4.z; p0 += (fmaxf(z,0.f) + NEG_SLOPE*fminf(z,0.f)) * att4.z;
            z  = v0.w + xr4.w; p0 += (fmaxf(z,0.f) + NEG_SLOPE*fminf(z,0.f)) * att4.w;
            p0 += __shfl_xor_sync(0xffffffffu, p0, 1);
            p0 += __shfl_xor_sync(0xffffffffu, p0, 2);

            const float mn = fmaxf(m, p0);
            const float em = __expf(m - mn);
            const float w0 = __expf(p0 - mn);
            d = d * em + w0;
            acc.x = acc.x * em + v0.x * w0;
            acc.y = acc.y * em + v0.y * w0;
            acc.z = acc.z * em + v0.z * w0;
            acc.w = acc.w * em + v0.w * w0;
            m = mn;
        }
    }

    const float inv = 1.0f / (d + 1e-16f);
    const float4 bias4 = reinterpret_cast<const float4*>(bias)[lane];
    const float4 x4 = *reinterpret_cast<const float4*>(x + (size_t)nid * DIM + lane * 4);
    float4 o;
    o.x = x4.x + fmaxf(acc.x * inv + bias4.x, 0.f);
    o.y = x4.y + fmaxf(acc.y * inv + bias4.y, 0.f);
    o.z = x4.z + fmaxf(acc.z * inv + bias4.z, 0.f);
    o.w = x4.w + fmaxf(acc.w * inv + bias4.w, 0.f);
    *reinterpret_cast<float4*>(out + (size_t)nid * DIM + lane * 4) = o;
}

// ---------------- launch ----------------
extern "C" void kernel_launch(void* const* d_in, const int* in_sizes, int n_in,
                              void* d_out, int out_size)
{
    const float* x    = (const float*)d_in[0];
    const int*   ei   = (const int*)d_in[1];
    const float* lng  = (const float*)d_in[2];
    const float* lnb  = (const float*)d_in[3];
    const float* Wl   = (const float*)d_in[4];
    const float* bl   = (const float*)d_in[5];
    const float* Wr   = (const float*)d_in[6];
    const float* br   = (const float*)d_in[7];
    const float* att  = (const float*)d_in[8];
    const float* bias = (const float*)d_in[9];
    float* out = (float*)d_out;

    // Lazy-created side stream + events (first call is the non-captured
    // correctness run, so creation never happens during graph capture).
    static cudaStream_t s_csr = nullptr;
    static cudaEvent_t  ev_fork = nullptr, ev_join = nullptr;
    if (!s_csr) {
        cudaStreamCreateWithFlags(&s_csr, cudaStreamNonBlocking);
        cudaEventCreateWithFlags(&ev_fork, cudaEventDisableTiming);
        cudaEventCreateWithFlags(&ev_join, cudaEventDisableTiming);
    }

    cudaFuncSetAttribute(ln_gemm_kernel, cudaFuncAttributeMaxDynamicSharedMemorySize, SM_TOTAL);

    // fork: CSR build on side stream
    cudaEventRecord(ev_fork, 0);
    cudaStreamWaitEvent(s_csr, ev_fork, 0);
    zero_kernel  <<<(N_NODES + 255) / 256, 256, 0, s_csr>>>();
    count_kernel <<<(E_EDGES + 255) / 256, 256, 0, s_csr>>>(ei);
    assign_kernel<<<(N_NODES + 255) / 256, 256, 0, s_csr>>>();
    fill_kernel  <<<(E_EDGES + 255) / 256, 256, 0, s_csr>>>(ei);
    cudaEventRecord(ev_join, s_csr);

    // main stream: W split + LN + mma GEMM
    prep_b_kernel<<<(256 * 128 + 255) / 256, 256>>>(Wl, Wr);
    ln_gemm_kernel<<<NTILES, 512, SM_TOTAL>>>(x, lng, lnb, bl, br);

    // join, then aggregate
    cudaStreamWaitEvent(0, ev_join, 0);
    agg_kernel<<<(N_NODES + 7) / 8, 256>>>(x, att, bias, out);
}